// round 7
// baseline (speedup 1.0000x reference)
#include <cuda_runtime.h>
#include <cuda_bf16.h>

#define BATCH 8
#define CHANS 4
#define H 512
#define W 512
#define NPIX (BATCH * H * W)          // 2,097,152
#define NROWS (BATCH * H)             // 4096
#define LOSS_BLOCKS (BATCH * (H / 2)) // 2048

typedef unsigned long long u64;

// Scratch: per-pixel horizontal distances (byte pairs: fg, bg). One of the two
// is always 0; the other is the distance to the nearest opposite-class pixel.
__device__ uchar2 g_rcol[NPIX];
__device__ double g_bsum[LOSS_BLOCKS];
__device__ unsigned g_count = 0;

// ---------------------------------------------------------------------------
// Kernel 1: horizontal distance to nearest opposite-class pixel.
// One warp per row, 16 px/lane, no shared memory, no __syncthreads.
// Transition bitmap E[q] = M[q] ^ M[q+1]; right dist = ffs, left dist = clz.
// ---------------------------------------------------------------------------
__global__ void rowdist_kernel(const int4* __restrict__ yt4) {
    const int lane = threadIdx.x & 31;
    const int warp = threadIdx.x >> 5;            // 8 warps/block
    const int row  = blockIdx.x * 8 + warp;

    // 16 pixels: 4 independent int4 loads (64B, MLP=4)
    const int4* p = yt4 + (size_t)row * 128 + lane * 4;
    int4 a = p[0], b = p[1], c = p[2], d = p[3];
    unsigned m =
          (unsigned)(a.x > 0)         | ((unsigned)(a.y > 0) << 1)
        | ((unsigned)(a.z > 0) << 2)  | ((unsigned)(a.w > 0) << 3)
        | ((unsigned)(b.x > 0) << 4)  | ((unsigned)(b.y > 0) << 5)
        | ((unsigned)(b.z > 0) << 6)  | ((unsigned)(b.w > 0) << 7)
        | ((unsigned)(c.x > 0) << 8)  | ((unsigned)(c.y > 0) << 9)
        | ((unsigned)(c.z > 0) << 10) | ((unsigned)(c.w > 0) << 11)
        | ((unsigned)(d.x > 0) << 12) | ((unsigned)(d.y > 0) << 13)
        | ((unsigned)(d.z > 0) << 14) | ((unsigned)(d.w > 0) << 15);

    unsigned m_m2 = __shfl_up_sync(0xFFFFFFFFu, m, 2);
    unsigned m_m1 = __shfl_up_sync(0xFFFFFFFFu, m, 1);
    unsigned m_p1 = __shfl_down_sync(0xFFFFFFFFu, m, 1);
    unsigned m_p2 = __shfl_down_sync(0xFFFFFFFFu, m, 2);
    unsigned m_p3 = __shfl_down_sync(0xFFFFFFFFu, m, 3);
    if (lane < 2)  { m_m2 = 0u; if (lane < 1) m_m1 = 0u; }
    if (lane > 28) { m_p3 = 0u; if (lane > 29) { m_p2 = 0u; if (lane > 30) m_p1 = 0u; } }

    // Mhi bit k <-> pixel 16*lane + k ;  Mlo bit k <-> pixel 16*lane - 32 + k
    u64 Mhi = (u64)m | ((u64)m_p1 << 16) | ((u64)m_p2 << 32) | ((u64)m_p3 << 48);
    u64 Mlo = (u64)m_m2 | ((u64)m_m1 << 16) | ((u64)m << 32) | ((u64)m_p1 << 48);
    u64 Ehi = Mhi ^ (Mhi >> 1);   // transition between pixel q and q+1
    u64 Elo = Mlo ^ (Mlo >> 1);

    // Edge masks: no transitions outside [0, 510].
    int kmaxr = 510 - 16 * lane;                  // only lanes 28..31 clip
    if (kmaxr < 63) Ehi &= (1ull << (kmaxr + 1)) - 1ull;
    if (lane == 0)      Elo &= ~0xFFFFFFFFull;    // valid k >= 32
    else if (lane == 1) Elo &= ~0xFFFFull;        // valid k >= 16
    Elo |= 1ull;                                  // left sentinel -> far

    u64 out[4] = {0ull, 0ull, 0ull, 0ull};
    #pragma unroll
    for (int j = 0; j < 16; ++j) {
        int rd = __ffsll((long long)((Ehi >> j) | (1ull << 40)));   // 1-based
        int ld = __clzll((long long)(Elo << (32 - j))) + 1;
        unsigned e = (unsigned)min(rd, ld);                         // exact e<=31
        unsigned pair = ((m >> j) & 1u) ? (e << 8) : e;             // (fg, bg)
        out[j >> 2] |= (u64)pair << (16 * (j & 3));
    }
    ulonglong2* dst = (ulonglong2*)g_rcol + (size_t)row * 64 + lane * 2;
    dst[0] = make_ulonglong2(out[0], out[1]);
    dst[1] = make_ulonglong2(out[2], out[3]);
}

// ---------------------------------------------------------------------------
// Kernel 2: vertical combine (SIMD bytewise, early exit) + softmax + weighted
// squared error + per-block reduction + fused last-block final reduce.
// 2 rows/block, 256 threads, 4 px/thread.
// ---------------------------------------------------------------------------
__global__ void loss_kernel(const float4* __restrict__ logits4,
                            float* __restrict__ outp) {
    const int t = threadIdx.x & 127;      // x-quad 0..127
    const int r = threadIdx.x >> 7;       // row in block 0..1
    const int y = blockIdx.y * 2 + r;
    const int b = blockIdx.z;

    // ---- logits loads first (dominant DRAM traffic, max MLP) ----
    const float4* lp = logits4 + ((size_t)b * CHANS * H + y) * 128 + t;
    float4 L0 = lp[0];
    float4 L1 = lp[(size_t)H * 128];
    float4 L2 = lp[2 * (size_t)H * 128];
    float4 L3 = lp[3 * (size_t)H * 128];

    // ---- vertical DT, SIMD bytewise on interleaved (fg,bg) byte pairs ----
    const u64* col = (const u64*)g_rcol + (size_t)b * H * 128 + t;
    u64 self = col[(size_t)y * 128];
    unsigned s0 = (unsigned)self;
    unsigned s1 = (unsigned)(self >> 32);

    #pragma unroll 1
    for (int d = 1; d <= 30; ++d) {
        unsigned mm = __vmaxu4(s0, s1);
        if (((mm + (127 - d) * 0x01010101u) & 0x80808080u) == 0u) break;
        u64 up = (y - d >= 0) ? col[(size_t)(y - d) * 128] : 0x7f7f7f7f7f7f7f7full;
        u64 dn = (y + d <  H) ? col[(size_t)(y + d) * 128] : 0x7f7f7f7f7f7f7f7full;
        unsigned dd = (unsigned)d * 0x01010101u;
        unsigned t0 = __vminu4((unsigned)up, (unsigned)dn);
        unsigned t1 = __vminu4((unsigned)(up >> 32), (unsigned)(dn >> 32));
        s0 = __vminu4(s0, __vmaxu4(t0, dd));
        s1 = __vminu4(s1, __vmaxu4(t1, dd));
    }

    unsigned fgb[4], bgb[4];
    fgb[0] = s0 & 255u;         bgb[0] = (s0 >> 8) & 255u;
    fgb[1] = (s0 >> 16) & 255u; bgb[1] = s0 >> 24;
    fgb[2] = s1 & 255u;         bgb[2] = (s1 >> 8) & 255u;
    fgb[3] = (s1 >> 16) & 255u; bgb[3] = s1 >> 24;

    float l0[4] = {L0.x, L0.y, L0.z, L0.w};
    float l1[4] = {L1.x, L1.y, L1.z, L1.w};
    float l2[4] = {L2.x, L2.y, L2.z, L2.w};
    float l3[4] = {L3.x, L3.y, L3.z, L3.w};

    float v = 0.0f;
    #pragma unroll
    for (int k = 0; k < 4; ++k) {
        float hi  = fmaxf(l1[k], l2[k]);
        float lo  = fminf(l1[k], l2[k]);
        float a   = fmaxf(hi, l3[k]);
        float sec = fminf(hi, l3[k]);
        float sum = 1.0f + __expf(lo - a) + __expf(sec - a) + __expf(l0[k] - a);
        float gp  = 1.0f / sum;

        float dfg = (fgb[k] <= 30u) ? (float)fgb[k] : 200.0f;
        float dbg = (bgb[k] <= 30u) ? (float)bgb[k] : 200.0f;
        float wmap = dfg * dfg + dbg * dbg;
        float gt = (fgb[k] == 0u) ? 1.0f : 0.0f;
        float diff = gp - gt;
        v += diff * diff * wmap;
    }

    // ---- deterministic block reduction (8 warps) ----
    #pragma unroll
    for (int o = 16; o > 0; o >>= 1) v += __shfl_down_sync(0xFFFFFFFFu, v, o);
    __shared__ float wsum[8];
    int lane = threadIdx.x & 31, wid = threadIdx.x >> 5;
    if (lane == 0) wsum[wid] = v;
    __syncthreads();

    __shared__ bool isLast;
    if (threadIdx.x == 0) {
        double s = 0.0;
        #pragma unroll
        for (int i = 0; i < 8; ++i) s += (double)wsum[i];
        g_bsum[blockIdx.z * gridDim.y + blockIdx.y] = s;
        __threadfence();
        unsigned prev = atomicAdd(&g_count, 1u);
        isLast = (prev == (unsigned)(LOSS_BLOCKS - 1));
    }
    __syncthreads();

    // ---- last block: deterministic fixed-order final reduction ----
    if (isLast) {
        __shared__ double sh[256];
        double s = 0.0;
        #pragma unroll
        for (int i = 0; i < LOSS_BLOCKS / 256; ++i)
            s += g_bsum[threadIdx.x + i * 256];
        sh[threadIdx.x] = s;
        __syncthreads();
        #pragma unroll
        for (int o = 128; o > 0; o >>= 1) {
            if (threadIdx.x < o) sh[threadIdx.x] += sh[threadIdx.x + o];
            __syncthreads();
        }
        if (threadIdx.x == 0) {
            outp[0] = (float)(sh[0] / (double)NPIX);
            g_count = 0;                  // reset for next graph replay
        }
    }
}

extern "C" void kernel_launch(void* const* d_in, const int* in_sizes, int n_in,
                              void* d_out, int out_size) {
    const float* logits = (const float*)d_in[0];
    const int*   y_true = (const int*)d_in[1];
    float*       out    = (float*)d_out;

    rowdist_kernel<<<NROWS / 8, 256>>>((const int4*)y_true);

    dim3 blk(256, 1, 1);
    dim3 grd(1, H / 2, BATCH);
    loss_kernel<<<grd, blk>>>((const float4*)logits, out);
}

// round 8
// speedup vs baseline: 1.0109x; 1.0109x over previous
#include <cuda_runtime.h>
#include <cuda_bf16.h>

#define BATCH 8
#define CHANS 4
#define H 512
#define W 512
#define NPIX (BATCH * H * W)          // 2,097,152
#define NROWS (BATCH * H)             // 4096
#define LOSS_BLOCKS (BATCH * (H / 2)) // 2048

typedef unsigned long long u64;
#define FARPAIR 0x7f7f7f7f7f7f7f7full

// Scratch: per-pixel horizontal distances (byte pairs: fg, bg). One of the two
// is always 0; the other is the distance to the nearest opposite-class pixel.
__device__ uchar2 g_rcol[NPIX];
__device__ double g_bsum[LOSS_BLOCKS];

// ---------------------------------------------------------------------------
// Kernel 1: horizontal distance to nearest opposite-class pixel.
// One warp per row, 16 px/lane, no shared memory, no __syncthreads.
// Transition bitmap E[q] = M[q] ^ M[q+1]; right dist = ffs, left dist = clz.
// ---------------------------------------------------------------------------
__global__ void rowdist_kernel(const int4* __restrict__ yt4) {
    const int lane = threadIdx.x & 31;
    const int warp = threadIdx.x >> 5;            // 8 warps/block
    const int row  = blockIdx.x * 8 + warp;

    // 16 pixels: 4 independent int4 loads (64B, MLP=4)
    const int4* p = yt4 + (size_t)row * 128 + lane * 4;
    int4 a = p[0], b = p[1], c = p[2], d = p[3];
    unsigned m =
          (unsigned)(a.x > 0)         | ((unsigned)(a.y > 0) << 1)
        | ((unsigned)(a.z > 0) << 2)  | ((unsigned)(a.w > 0) << 3)
        | ((unsigned)(b.x > 0) << 4)  | ((unsigned)(b.y > 0) << 5)
        | ((unsigned)(b.z > 0) << 6)  | ((unsigned)(b.w > 0) << 7)
        | ((unsigned)(c.x > 0) << 8)  | ((unsigned)(c.y > 0) << 9)
        | ((unsigned)(c.z > 0) << 10) | ((unsigned)(c.w > 0) << 11)
        | ((unsigned)(d.x > 0) << 12) | ((unsigned)(d.y > 0) << 13)
        | ((unsigned)(d.z > 0) << 14) | ((unsigned)(d.w > 0) << 15);

    unsigned m_m2 = __shfl_up_sync(0xFFFFFFFFu, m, 2);
    unsigned m_m1 = __shfl_up_sync(0xFFFFFFFFu, m, 1);
    unsigned m_p1 = __shfl_down_sync(0xFFFFFFFFu, m, 1);
    unsigned m_p2 = __shfl_down_sync(0xFFFFFFFFu, m, 2);
    unsigned m_p3 = __shfl_down_sync(0xFFFFFFFFu, m, 3);
    if (lane < 2)  { m_m2 = 0u; if (lane < 1) m_m1 = 0u; }
    if (lane > 28) { m_p3 = 0u; if (lane > 29) { m_p2 = 0u; if (lane > 30) m_p1 = 0u; } }

    // Mhi bit k <-> pixel 16*lane + k ;  Mlo bit k <-> pixel 16*lane - 32 + k
    u64 Mhi = (u64)m | ((u64)m_p1 << 16) | ((u64)m_p2 << 32) | ((u64)m_p3 << 48);
    u64 Mlo = (u64)m_m2 | ((u64)m_m1 << 16) | ((u64)m << 32) | ((u64)m_p1 << 48);
    u64 Ehi = Mhi ^ (Mhi >> 1);   // transition between pixel q and q+1
    u64 Elo = Mlo ^ (Mlo >> 1);

    // Edge masks: no transitions outside [0, 510].
    int kmaxr = 510 - 16 * lane;                  // only lanes 28..31 clip
    if (kmaxr < 63) Ehi &= (1ull << (kmaxr + 1)) - 1ull;
    if (lane == 0)      Elo &= ~0xFFFFFFFFull;    // valid k >= 32
    else if (lane == 1) Elo &= ~0xFFFFull;        // valid k >= 16
    Elo |= 1ull;                                  // left sentinel -> far

    u64 out[4] = {0ull, 0ull, 0ull, 0ull};
    #pragma unroll
    for (int j = 0; j < 16; ++j) {
        int rd = __ffsll((long long)((Ehi >> j) | (1ull << 40)));   // 1-based
        int ld = __clzll((long long)(Elo << (32 - j))) + 1;
        unsigned e = (unsigned)min(rd, ld);                         // exact e<=31
        unsigned pair = ((m >> j) & 1u) ? (e << 8) : e;             // (fg, bg)
        out[j >> 2] |= (u64)pair << (16 * (j & 3));
    }
    ulonglong2* dst = (ulonglong2*)g_rcol + (size_t)row * 64 + lane * 2;
    dst[0] = make_ulonglong2(out[0], out[1]);
    dst[1] = make_ulonglong2(out[2], out[3]);
}

// ---------------------------------------------------------------------------
// Kernel 2: vertical combine (SIMD bytewise, 2 steps per latency trip) +
// softmax + weighted SE + per-block reduction. 2 rows/block, 256 thr, 4 px/thr.
// ---------------------------------------------------------------------------
__global__ void loss_kernel(const float4* __restrict__ logits4) {
    const int t = threadIdx.x & 127;      // x-quad 0..127
    const int r = threadIdx.x >> 7;       // row in block 0..1
    const int y = blockIdx.y * 2 + r;
    const int b = blockIdx.z;

    // ---- logits loads first (dominant DRAM traffic, max MLP) ----
    const float4* lp = logits4 + ((size_t)b * CHANS * H + y) * 128 + t;
    float4 L0 = lp[0];
    float4 L1 = lp[(size_t)H * 128];
    float4 L2 = lp[2 * (size_t)H * 128];
    float4 L3 = lp[3 * (size_t)H * 128];

    // kick off the DT self-load too
    const u64* col = (const u64*)g_rcol + (size_t)b * H * 128 + t;
    u64 self = col[(size_t)y * 128];

    // ---- softmax now (frees 12 registers across the DT loop) ----
    float l0[4] = {L0.x, L0.y, L0.z, L0.w};
    float l1[4] = {L1.x, L1.y, L1.z, L1.w};
    float l2[4] = {L2.x, L2.y, L2.z, L2.w};
    float l3[4] = {L3.x, L3.y, L3.z, L3.w};
    float gp[4];
    #pragma unroll
    for (int k = 0; k < 4; ++k) {
        float hi  = fmaxf(l1[k], l2[k]);
        float lo  = fminf(l1[k], l2[k]);
        float a   = fmaxf(hi, l3[k]);
        float sec = fminf(hi, l3[k]);
        float sum = 1.0f + __expf(lo - a) + __expf(sec - a) + __expf(l0[k] - a);
        gp[k] = 1.0f / sum;
    }

    // ---- vertical DT: two distance steps per exit check (4 loads in flight) ----
    unsigned s0 = (unsigned)self;
    unsigned s1 = (unsigned)(self >> 32);

    #pragma unroll 1
    for (int d = 1; d <= 29; d += 2) {
        // break if all bytes <= d (candidates from steps d, d+1 are >= d)
        unsigned mm = __vmaxu4(s0, s1);
        if (((mm + (127 - d) * 0x01010101u) & 0x80808080u) == 0u) break;
        u64 up1 = (y - d     >= 0) ? col[(size_t)(y - d)     * 128] : FARPAIR;
        u64 dn1 = (y + d     <  H) ? col[(size_t)(y + d)     * 128] : FARPAIR;
        u64 up2 = (y - d - 1 >= 0) ? col[(size_t)(y - d - 1) * 128] : FARPAIR;
        u64 dn2 = (y + d + 1 <  H) ? col[(size_t)(y + d + 1) * 128] : FARPAIR;
        unsigned dd1 = (unsigned)d * 0x01010101u;
        unsigned dd2 = dd1 + 0x01010101u;
        unsigned a0 = __vminu4((unsigned)up1, (unsigned)dn1);
        unsigned a1 = __vminu4((unsigned)(up1 >> 32), (unsigned)(dn1 >> 32));
        unsigned b0 = __vminu4((unsigned)up2, (unsigned)dn2);
        unsigned b1 = __vminu4((unsigned)(up2 >> 32), (unsigned)(dn2 >> 32));
        s0 = __vminu4(s0, __vminu4(__vmaxu4(a0, dd1), __vmaxu4(b0, dd2)));
        s1 = __vminu4(s1, __vminu4(__vmaxu4(a1, dd1), __vmaxu4(b1, dd2)));
    }

    unsigned fgb[4], bgb[4];
    fgb[0] = s0 & 255u;         bgb[0] = (s0 >> 8) & 255u;
    fgb[1] = (s0 >> 16) & 255u; bgb[1] = s0 >> 24;
    fgb[2] = s1 & 255u;         bgb[2] = (s1 >> 8) & 255u;
    fgb[3] = (s1 >> 16) & 255u; bgb[3] = s1 >> 24;

    float v = 0.0f;
    #pragma unroll
    for (int k = 0; k < 4; ++k) {
        float dfg = (fgb[k] <= 30u) ? (float)fgb[k] : 200.0f;
        float dbg = (bgb[k] <= 30u) ? (float)bgb[k] : 200.0f;
        float wmap = dfg * dfg + dbg * dbg;
        float gt = (fgb[k] == 0u) ? 1.0f : 0.0f;
        float diff = gp[k] - gt;
        v += diff * diff * wmap;
    }

    // ---- deterministic block reduction (8 warps) ----
    #pragma unroll
    for (int o = 16; o > 0; o >>= 1) v += __shfl_down_sync(0xFFFFFFFFu, v, o);
    __shared__ float wsum[8];
    int lane = threadIdx.x & 31, wid = threadIdx.x >> 5;
    if (lane == 0) wsum[wid] = v;
    __syncthreads();
    if (threadIdx.x == 0) {
        double s = 0.0;
        #pragma unroll
        for (int i = 0; i < 8; ++i) s += (double)wsum[i];
        g_bsum[blockIdx.z * gridDim.y + blockIdx.y] = s;
    }
}

// Kernel 3: deterministic final reduction + mean.
__global__ void final_kernel(float* __restrict__ out) {
    __shared__ double sh[256];
    double s = 0.0;
    #pragma unroll
    for (int i = 0; i < LOSS_BLOCKS / 256; ++i)
        s += g_bsum[threadIdx.x + i * 256];
    sh[threadIdx.x] = s;
    __syncthreads();
    #pragma unroll
    for (int o = 128; o > 0; o >>= 1) {
        if (threadIdx.x < o) sh[threadIdx.x] += sh[threadIdx.x + o];
        __syncthreads();
    }
    if (threadIdx.x == 0) out[0] = (float)(sh[0] / (double)NPIX);
}

extern "C" void kernel_launch(void* const* d_in, const int* in_sizes, int n_in,
                              void* d_out, int out_size) {
    const float* logits = (const float*)d_in[0];
    const int*   y_true = (const int*)d_in[1];
    float*       out    = (float*)d_out;

    rowdist_kernel<<<NROWS / 8, 256>>>((const int4*)y_true);

    dim3 blk(256, 1, 1);
    dim3 grd(1, H / 2, BATCH);
    loss_kernel<<<grd, blk>>>((const float4*)logits);

    final_kernel<<<1, 256>>>(out);
}

// round 9
// speedup vs baseline: 1.0140x; 1.0031x over previous
#include <cuda_runtime.h>
#include <cuda_bf16.h>

#define BATCH 8
#define CHANS 4
#define H 512
#define W 512
#define NPIX (BATCH * H * W)          // 2,097,152
#define NROWS (BATCH * H)             // 4096
#define LOSS_BLOCKS (BATCH * (H / 2)) // 2048

typedef unsigned long long u64;
#define FARPAIR 0x7f7f7f7f7f7f7f7full

// Scratch: per-pixel horizontal distances (byte pairs: fg, bg). One of the two
// is always 0; the other is the distance to the nearest opposite-class pixel.
__device__ uchar2 g_rcol[NPIX];
__device__ double g_bsum[LOSS_BLOCKS];

// ---------------------------------------------------------------------------
// Kernel 1: horizontal distance to nearest opposite-class pixel.
// 4 rows/block (256 thr), 64 lanes/row, 8 px/lane. Row class-mask assembled as
// bytes in padded smem; each lane then reads one aligned 16B window that covers
// its 8 pixels' full +/-30 search range. One __syncthreads total.
// ---------------------------------------------------------------------------
__global__ void rowdist_kernel(const int4* __restrict__ yt4) {
    // padded words: [0] = 4 guard bytes, [1..16] = 64 mask bytes, [17..19] = guards
    __shared__ unsigned m32[4][20];
    const int tid = threadIdx.x;
    const int r  = tid >> 6;              // row in block 0..3
    const int gl = tid & 63;              // byte index in row, pixels 8gl..8gl+7
    const int row = blockIdx.x * 4 + r;

    // 8 pixels: 2 independent int4 loads (32B)
    const int4* p = yt4 + (size_t)row * 128 + gl * 2;
    int4 a = p[0], b = p[1];
    unsigned m8 =
          (unsigned)(a.x > 0)        | ((unsigned)(a.y > 0) << 1)
        | ((unsigned)(a.z > 0) << 2) | ((unsigned)(a.w > 0) << 3)
        | ((unsigned)(b.x > 0) << 4) | ((unsigned)(b.y > 0) << 5)
        | ((unsigned)(b.z > 0) << 6) | ((unsigned)(b.w > 0) << 7);

    if (tid < 4) { m32[tid][0] = 0u; }
    if (tid >= 4 && tid < 16) { m32[tid & 3][17 + (tid >> 2) - 1] = 0u; }
    ((unsigned char*)&m32[r][1])[gl] = (unsigned char)m8;
    __syncthreads();

    // 16B aligned window starting at padded word (gl>>2): padded bits W0..W0+127
    const unsigned* base = &m32[r][0];
    const int w0 = gl >> 2;
    u64 lo = (u64)base[w0]     | ((u64)base[w0 + 1] << 32);
    u64 hi = (u64)base[w0 + 2] | ((u64)base[w0 + 3] << 32);

    // E bit w = transition between window bits w and w+1
    u64 Elo = lo ^ ((lo >> 1) | (hi << 63));
    u64 Ehi = hi ^ (hi >> 1);

    // Guard-induced fake transitions that could fake a distance <= 30:
    // padded bit 31 (before pixel 0) and padded bit 543 (after pixel 511).
    if (gl < 4)   Elo &= ~(1ull << 31);   // W0=0   -> w=31
    if (gl >= 60) Elo &= ~(1ull << 63);   // W0=480 -> w=63
    // (all other fakes map to e >= 31 == far; far-is-far downstream)

    const int o = 32 + (gl & 3) * 8;      // window bit of pixel p0 (32..56)
    u64 out[2] = {0ull, 0ull};
    #pragma unroll
    for (int j = 0; j < 8; ++j) {
        const int sh = o + j;             // 32..63
        // right: dist d <-> E bit sh+d-1 ; sentinel keeps "none" -> >30
        u64 R = (Elo >> sh) | (Ehi << (64 - sh)) | (1ull << 40);
        int rd = __ffsll((long long)R);   // 1-based = distance
        // left: dist d <-> E bit sh-d ; put bit sh-1 at MSB, sentinel at bit 0
        u64 L = (Elo << (64 - sh)) | 1ull;
        int ld = __clzll((long long)L) + 1;
        unsigned e = (unsigned)min(rd, ld);              // exact for e<=30
        unsigned pair = ((lo >> sh) & 1ull) ? (e << 8) : e;  // (fg, bg) bytes
        out[j >> 2] |= (u64)pair << (16 * (j & 3));
    }
    ((ulonglong2*)g_rcol)[(size_t)row * 64 + gl] = make_ulonglong2(out[0], out[1]);
}

// ---------------------------------------------------------------------------
// Kernel 2: vertical combine (SIMD bytewise, 2 steps per latency trip) +
// softmax + weighted SE + per-block reduction. 2 rows/block, 256 thr, 4 px/thr.
// ---------------------------------------------------------------------------
__global__ void __launch_bounds__(256, 8)
loss_kernel(const float4* __restrict__ logits4) {
    const int t = threadIdx.x & 127;      // x-quad 0..127
    const int r = threadIdx.x >> 7;       // row in block 0..1
    const int y = blockIdx.y * 2 + r;
    const int b = blockIdx.z;

    // ---- logits loads first (dominant DRAM traffic, max MLP) ----
    const float4* lp = logits4 + ((size_t)b * CHANS * H + y) * 128 + t;
    float4 L0 = lp[0];
    float4 L1 = lp[(size_t)H * 128];
    float4 L2 = lp[2 * (size_t)H * 128];
    float4 L3 = lp[3 * (size_t)H * 128];

    const u64* col = (const u64*)g_rcol + (size_t)b * H * 128 + t;
    u64 self = col[(size_t)y * 128];

    // ---- softmax now (frees 12 registers across the DT loop) ----
    float l0[4] = {L0.x, L0.y, L0.z, L0.w};
    float l1[4] = {L1.x, L1.y, L1.z, L1.w};
    float l2[4] = {L2.x, L2.y, L2.z, L2.w};
    float l3[4] = {L3.x, L3.y, L3.z, L3.w};
    float gp[4];
    #pragma unroll
    for (int k = 0; k < 4; ++k) {
        float hi  = fmaxf(l1[k], l2[k]);
        float lo  = fminf(l1[k], l2[k]);
        float aa  = fmaxf(hi, l3[k]);
        float sec = fminf(hi, l3[k]);
        float sum = 1.0f + __expf(lo - aa) + __expf(sec - aa) + __expf(l0[k] - aa);
        gp[k] = 1.0f / sum;
    }

    // ---- vertical DT: two distance steps per exit check (4 loads in flight) ----
    unsigned s0 = (unsigned)self;
    unsigned s1 = (unsigned)(self >> 32);

    #pragma unroll 1
    for (int d = 1; d <= 29; d += 2) {
        unsigned mm = __vmaxu4(s0, s1);
        if (((mm + (127 - d) * 0x01010101u) & 0x80808080u) == 0u) break;
        u64 up1 = (y - d     >= 0) ? col[(size_t)(y - d)     * 128] : FARPAIR;
        u64 dn1 = (y + d     <  H) ? col[(size_t)(y + d)     * 128] : FARPAIR;
        u64 up2 = (y - d - 1 >= 0) ? col[(size_t)(y - d - 1) * 128] : FARPAIR;
        u64 dn2 = (y + d + 1 <  H) ? col[(size_t)(y + d + 1) * 128] : FARPAIR;
        unsigned dd1 = (unsigned)d * 0x01010101u;
        unsigned dd2 = dd1 + 0x01010101u;
        unsigned a0 = __vminu4((unsigned)up1, (unsigned)dn1);
        unsigned a1 = __vminu4((unsigned)(up1 >> 32), (unsigned)(dn1 >> 32));
        unsigned b0 = __vminu4((unsigned)up2, (unsigned)dn2);
        unsigned b1 = __vminu4((unsigned)(up2 >> 32), (unsigned)(dn2 >> 32));
        s0 = __vminu4(s0, __vminu4(__vmaxu4(a0, dd1), __vmaxu4(b0, dd2)));
        s1 = __vminu4(s1, __vminu4(__vmaxu4(a1, dd1), __vmaxu4(b1, dd2)));
    }

    unsigned fgb[4], bgb[4];
    fgb[0] = s0 & 255u;         bgb[0] = (s0 >> 8) & 255u;
    fgb[1] = (s0 >> 16) & 255u; bgb[1] = s0 >> 24;
    fgb[2] = s1 & 255u;         bgb[2] = (s1 >> 8) & 255u;
    fgb[3] = (s1 >> 16) & 255u; bgb[3] = s1 >> 24;

    float v = 0.0f;
    #pragma unroll
    for (int k = 0; k < 4; ++k) {
        float dfg = (fgb[k] <= 30u) ? (float)fgb[k] : 200.0f;
        float dbg = (bgb[k] <= 30u) ? (float)bgb[k] : 200.0f;
        float wmap = dfg * dfg + dbg * dbg;
        float gt = (fgb[k] == 0u) ? 1.0f : 0.0f;
        float diff = gp[k] - gt;
        v += diff * diff * wmap;
    }

    // ---- deterministic block reduction (8 warps) ----
    #pragma unroll
    for (int o = 16; o > 0; o >>= 1) v += __shfl_down_sync(0xFFFFFFFFu, v, o);
    __shared__ float wsum[8];
    int lane = threadIdx.x & 31, wid = threadIdx.x >> 5;
    if (lane == 0) wsum[wid] = v;
    __syncthreads();
    if (threadIdx.x == 0) {
        double s = 0.0;
        #pragma unroll
        for (int i = 0; i < 8; ++i) s += (double)wsum[i];
        g_bsum[blockIdx.z * gridDim.y + blockIdx.y] = s;
    }
}

// Kernel 3: deterministic final reduction + mean.
__global__ void final_kernel(float* __restrict__ out) {
    __shared__ double sh[256];
    double s = 0.0;
    #pragma unroll
    for (int i = 0; i < LOSS_BLOCKS / 256; ++i)
        s += g_bsum[threadIdx.x + i * 256];
    sh[threadIdx.x] = s;
    __syncthreads();
    #pragma unroll
    for (int o = 128; o > 0; o >>= 1) {
        if (threadIdx.x < o) sh[threadIdx.x] += sh[threadIdx.x + o];
        __syncthreads();
    }
    if (threadIdx.x == 0) out[0] = (float)(sh[0] / (double)NPIX);
}

extern "C" void kernel_launch(void* const* d_in, const int* in_sizes, int n_in,
                              void* d_out, int out_size) {
    const float* logits = (const float*)d_in[0];
    const int*   y_true = (const int*)d_in[1];
    float*       out    = (float*)d_out;

    rowdist_kernel<<<NROWS / 4, 256>>>((const int4*)y_true);

    dim3 blk(256, 1, 1);
    dim3 grd(1, H / 2, BATCH);
    loss_kernel<<<grd, blk>>>((const float4*)logits);

    final_kernel<<<1, 256>>>(out);
}

// round 10
// speedup vs baseline: 1.1168x; 1.1014x over previous
#include <cuda_runtime.h>
#include <cuda_bf16.h>

#define BATCH 8
#define CHANS 4
#define H 512
#define W 512
#define NPIX (BATCH * H * W)          // 2,097,152
#define NROWS (BATCH * H)             // 4096
#define LOSS_BLOCKS (BATCH * (H / 2)) // 2048

typedef unsigned long long u64;
#define FARPAIR 0x7f7f7f7f7f7f7f7full

// Scratch: per-pixel horizontal distances (byte pairs: fg, bg). One of the two
// is always 0; the other is the distance to the nearest opposite-class pixel.
__device__ uchar2 g_rcol[NPIX];
__device__ double g_bsum[LOSS_BLOCKS];

// ---------------------------------------------------------------------------
// Kernel 1: horizontal distance to nearest opposite-class pixel.
// 4 rows/block (256 thr), 64 lanes/row, 8 px/lane. Row class mask assembled as
// bytes in padded smem; per-pixel search uses 32-bit funnel-shift windows over
// the transition bitmap (1 SHF per direction), ffs/clz 32-bit.
// ---------------------------------------------------------------------------
__global__ void rowdist_kernel(const int4* __restrict__ yt4) {
    // padded words: [0] = guard, [1..16] = 512 mask bits, [17..19] = guards
    __shared__ unsigned m32[4][20];
    const int tid = threadIdx.x;
    const int r  = tid >> 6;              // row in block 0..3
    const int gl = tid & 63;              // byte index in row, pixels 8gl..8gl+7
    const int row = blockIdx.x * 4 + r;

    // 8 pixels: 2 independent int4 loads (32B)
    const int4* pp = yt4 + (size_t)row * 128 + gl * 2;
    int4 a = pp[0], b = pp[1];

    // labels are 0..3: gather low bytes (PRMT), then nonzero-per-byte bit trick
    unsigned ta = __byte_perm((unsigned)a.x, (unsigned)a.y, 0x4040);
    unsigned tb = __byte_perm((unsigned)a.z, (unsigned)a.w, 0x4040);
    unsigned ua = __byte_perm(ta, tb, 0x5410);            // [x0,y0,z0,w0]
    unsigned tc = __byte_perm((unsigned)b.x, (unsigned)b.y, 0x4040);
    unsigned td = __byte_perm((unsigned)b.z, (unsigned)b.w, 0x4040);
    unsigned ub = __byte_perm(tc, td, 0x5410);
    ua = (ua | (ua >> 1)) & 0x01010101u;                  // byte -> 0/1
    ub = (ub | (ub >> 1)) & 0x01010101u;
    unsigned m8 = (((ua * 0x01020408u) >> 24) & 0xFu)
                | (((ub * 0x01020408u) >> 20) & 0xF0u);

    if (tid < 4) { m32[tid][0] = 0u; }
    if (tid >= 4 && tid < 16) { m32[tid & 3][17 + (tid >> 2) - 1] = 0u; }
    ((unsigned char*)&m32[r][1])[gl] = (unsigned char)m8;
    __syncthreads();

    // window words w0..w0+3 (window bit w <-> padded bit 32*w0 + w)
    const unsigned* base = &m32[r][gl >> 2];
    unsigned m0 = base[0], m1 = base[1], m2 = base[2], m3 = base[3];

    // transition words: e_i bit k = M bit 32i+k ^ M bit 32i+k+1
    unsigned e0 = m0 ^ __funnelshift_r(m0, m1, 1);
    unsigned e1 = m1 ^ __funnelshift_r(m1, m2, 1);
    unsigned e2 = m2 ^ __funnelshift_r(m2, m3, 1);

    // guard-induced fake transitions that could fake a distance <= 30:
    // padded bit 31 (guard|pixel0) and padded bit 543 (pixel511|guard)
    if (gl < 4)   e0 &= 0x7FFFFFFFu;      // w0=0  -> e0 bit 31
    if (gl >= 60) e1 &= 0x7FFFFFFFu;      // w0=15 -> e1 bit 31
    // (other fakes map outside all consulted windows: R32 max bit = 94 < 95)

    const int pb = (gl & 3) * 8;          // pixel p0 offset within e1 (0..24)
    u64 out[2] = {0ull, 0ull};
    #pragma unroll
    for (int j = 0; j < 8; ++j) {
        const int p = pb + j;             // 0..31
        unsigned R32 = __funnelshift_r(e1, e2, p);   // E bits sh..sh+31
        unsigned L32 = __funnelshift_r(e0, e1, p);   // E bits sh-32..sh-1
        int rd = __ffs((int)(R32 | 0x80000000u));    // 1..32 (32 = far)
        int ld = __clz((int)(L32 | 1u)) + 1;         // 1..32 (32 = far)
        unsigned e = (unsigned)min(rd, ld);          // exact for e<=30
        unsigned pair = ((m1 >> p) & 1u) ? (e << 8) : e;  // (fg, bg) bytes
        out[j >> 2] |= (u64)pair << (16 * (j & 3));
    }
    ((ulonglong2*)g_rcol)[(size_t)row * 64 + gl] = make_ulonglong2(out[0], out[1]);
}

// ---------------------------------------------------------------------------
// Kernel 2: vertical combine (SIMD bytewise, 2 steps per latency trip) +
// softmax + weighted SE + per-block reduction. 2 rows/block, 256 thr, 4 px/thr.
// ---------------------------------------------------------------------------
__global__ void __launch_bounds__(256, 8)
loss_kernel(const float4* __restrict__ logits4) {
    const int t = threadIdx.x & 127;      // x-quad 0..127
    const int r = threadIdx.x >> 7;       // row in block 0..1
    const int y = blockIdx.y * 2 + r;
    const int b = blockIdx.z;

    // ---- logits loads first (dominant DRAM traffic, max MLP) ----
    const float4* lp = logits4 + ((size_t)b * CHANS * H + y) * 128 + t;
    float4 L0 = lp[0];
    float4 L1 = lp[(size_t)H * 128];
    float4 L2 = lp[2 * (size_t)H * 128];
    float4 L3 = lp[3 * (size_t)H * 128];

    const u64* col = (const u64*)g_rcol + (size_t)b * H * 128 + t;
    u64 self = col[(size_t)y * 128];

    // ---- softmax now (frees 12 registers across the DT loop) ----
    float l0[4] = {L0.x, L0.y, L0.z, L0.w};
    float l1[4] = {L1.x, L1.y, L1.z, L1.w};
    float l2[4] = {L2.x, L2.y, L2.z, L2.w};
    float l3[4] = {L3.x, L3.y, L3.z, L3.w};
    float gp[4];
    #pragma unroll
    for (int k = 0; k < 4; ++k) {
        float hi  = fmaxf(l1[k], l2[k]);
        float lo  = fminf(l1[k], l2[k]);
        float aa  = fmaxf(hi, l3[k]);
        float sec = fminf(hi, l3[k]);
        float sum = 1.0f + __expf(lo - aa) + __expf(sec - aa) + __expf(l0[k] - aa);
        gp[k] = 1.0f / sum;
    }

    // ---- vertical DT: two distance steps per exit check (4 loads in flight) ----
    unsigned s0 = (unsigned)self;
    unsigned s1 = (unsigned)(self >> 32);

    #pragma unroll 1
    for (int d = 1; d <= 29; d += 2) {
        unsigned mm = __vmaxu4(s0, s1);
        if (((mm + (127 - d) * 0x01010101u) & 0x80808080u) == 0u) break;
        u64 up1 = (y - d     >= 0) ? col[(size_t)(y - d)     * 128] : FARPAIR;
        u64 dn1 = (y + d     <  H) ? col[(size_t)(y + d)     * 128] : FARPAIR;
        u64 up2 = (y - d - 1 >= 0) ? col[(size_t)(y - d - 1) * 128] : FARPAIR;
        u64 dn2 = (y + d + 1 <  H) ? col[(size_t)(y + d + 1) * 128] : FARPAIR;
        unsigned dd1 = (unsigned)d * 0x01010101u;
        unsigned dd2 = dd1 + 0x01010101u;
        unsigned a0 = __vminu4((unsigned)up1, (unsigned)dn1);
        unsigned a1 = __vminu4((unsigned)(up1 >> 32), (unsigned)(dn1 >> 32));
        unsigned b0 = __vminu4((unsigned)up2, (unsigned)dn2);
        unsigned b1 = __vminu4((unsigned)(up2 >> 32), (unsigned)(dn2 >> 32));
        s0 = __vminu4(s0, __vminu4(__vmaxu4(a0, dd1), __vmaxu4(b0, dd2)));
        s1 = __vminu4(s1, __vminu4(__vmaxu4(a1, dd1), __vmaxu4(b1, dd2)));
    }

    unsigned fgb[4], bgb[4];
    fgb[0] = s0 & 255u;         bgb[0] = (s0 >> 8) & 255u;
    fgb[1] = (s0 >> 16) & 255u; bgb[1] = s0 >> 24;
    fgb[2] = s1 & 255u;         bgb[2] = (s1 >> 8) & 255u;
    fgb[3] = (s1 >> 16) & 255u; bgb[3] = s1 >> 24;

    float v = 0.0f;
    #pragma unroll
    for (int k = 0; k < 4; ++k) {
        float dfg = (fgb[k] <= 30u) ? (float)fgb[k] : 200.0f;
        float dbg = (bgb[k] <= 30u) ? (float)bgb[k] : 200.0f;
        float wmap = dfg * dfg + dbg * dbg;
        float gt = (fgb[k] == 0u) ? 1.0f : 0.0f;
        float diff = gp[k] - gt;
        v += diff * diff * wmap;
    }

    // ---- deterministic block reduction (8 warps) ----
    #pragma unroll
    for (int o = 16; o > 0; o >>= 1) v += __shfl_down_sync(0xFFFFFFFFu, v, o);
    __shared__ float wsum[8];
    int lane = threadIdx.x & 31, wid = threadIdx.x >> 5;
    if (lane == 0) wsum[wid] = v;
    __syncthreads();
    if (threadIdx.x == 0) {
        double s = 0.0;
        #pragma unroll
        for (int i = 0; i < 8; ++i) s += (double)wsum[i];
        g_bsum[blockIdx.z * gridDim.y + blockIdx.y] = s;
    }
}

// Kernel 3: deterministic final reduction + mean.
__global__ void final_kernel(float* __restrict__ out) {
    __shared__ double sh[256];
    double s = 0.0;
    #pragma unroll
    for (int i = 0; i < LOSS_BLOCKS / 256; ++i)
        s += g_bsum[threadIdx.x + i * 256];
    sh[threadIdx.x] = s;
    __syncthreads();
    #pragma unroll
    for (int o = 128; o > 0; o >>= 1) {
        if (threadIdx.x < o) sh[threadIdx.x] += sh[threadIdx.x + o];
        __syncthreads();
    }
    if (threadIdx.x == 0) out[0] = (float)(sh[0] / (double)NPIX);
}

extern "C" void kernel_launch(void* const* d_in, const int* in_sizes, int n_in,
                              void* d_out, int out_size) {
    const float* logits = (const float*)d_in[0];
    const int*   y_true = (const int*)d_in[1];
    float*       out    = (float*)d_out;

    rowdist_kernel<<<NROWS / 4, 256>>>((const int4*)y_true);

    dim3 blk(256, 1, 1);
    dim3 grd(1, H / 2, BATCH);
    loss_kernel<<<grd, blk>>>((const float4*)logits);

    final_kernel<<<1, 256>>>(out);
}